// round 1
// baseline (speedup 1.0000x reference)
#include <cuda_runtime.h>

// Sobel edge magnitude + channel mean.
// x: [B=16, C=64, H=256, W=256] f32 -> out: [B,1,H,W] f32
//
// Separable factorization per row i:
//   p_i(w) = x[i][w+1] - x[i][w-1]
//   q_i(w) = x[i][w-1] + 2*x[i][w] + x[i][w+1]
// Then for output row r:
//   gx(r) = p_r + 2*p_{r+1} + p_{r+2}
//   gy(r) = q_{r+2} - q_r
//
// Warp covers 128 columns (float4/lane) x R rows, rolling p/q in registers.
// 8 warps per block each handle 8 channels (c = wid + 8k) of the SAME spatial
// tile; partials are combined through a 32KB smem buffer at the end.

#define BB 16
#define CC 64
#define HH 256
#define WW 256
#define RR 8          // output rows per tile
#define NWARPS 8      // warps per block (channel stride)
#define TW 128        // columns per warp tile (32 lanes * 4)

__device__ __forceinline__ float sqrt_approx(float v) {
    float y;
    asm("sqrt.approx.f32 %0, %1;" : "=f"(y) : "f"(v));
    return y;
}

__global__ __launch_bounds__(256, 2)
void sobel_mean_kernel(const float* __restrict__ x, float* __restrict__ out) {
    const int wq   = blockIdx.x;   // column tile: 0..1
    const int hs   = blockIdx.y;   // row strip:   0..31
    const int b    = blockIdx.z;   // batch:       0..15
    const int tid  = threadIdx.x;
    const int wid  = tid >> 5;
    const int lane = tid & 31;

    const int gw4 = wq * TW + lane * 4;  // first of this lane's 4 columns
    const int gh0 = hs * RR;             // first output row of the strip

    __shared__ float s_acc[NWARPS][RR * TW];   // 32 KB

    float4 acc[RR];
#pragma unroll
    for (int r = 0; r < RR; r++) acc[r] = make_float4(0.f, 0.f, 0.f, 0.f);

    const unsigned FULL = 0xFFFFFFFFu;
    const bool has_left  = (gw4 != 0);        // only consulted on lane 0
    const bool has_right = (gw4 + 4 != WW);   // only consulted on lane 31

#pragma unroll 1
    for (int k = 0; k < CC / NWARPS; k++) {
        const int c = wid + NWARPS * k;
        const float* __restrict__ plane =
            x + ((size_t)(b * CC + c)) * (HH * WW);

        float4 p0, p1, q0, q1;   // rows i-2, i-1 (garbage until i>=2, unused)
        p0 = p1 = q0 = q1 = make_float4(0.f, 0.f, 0.f, 0.f);

#pragma unroll
        for (int i = 0; i < RR + 2; i++) {
            const int gh = gh0 - 1 + i;
            const bool inb = (gh >= 0) && (gh < HH);

            float4 v = make_float4(0.f, 0.f, 0.f, 0.f);
            if (inb) v = *reinterpret_cast<const float4*>(plane + gh * WW + gw4);

            float lft = __shfl_up_sync(FULL, v.w, 1);
            float rgt = __shfl_down_sync(FULL, v.x, 1);
            if (lane == 0)
                lft = (has_left && inb) ? plane[gh * WW + gw4 - 1] : 0.f;
            if (lane == 31)
                rgt = (has_right && inb) ? plane[gh * WW + gw4 + 4] : 0.f;

            float4 p, q;
            p.x = v.y - lft;  p.y = v.z - v.x;
            p.z = v.w - v.y;  p.w = rgt - v.z;
            q.x = fmaf(2.f, v.x, lft)  + v.y;
            q.y = fmaf(2.f, v.y, v.x)  + v.z;
            q.z = fmaf(2.f, v.z, v.y)  + v.w;
            q.w = fmaf(2.f, v.w, v.z)  + rgt;

            if (i >= 2) {
                const int r = i - 2;
                float gxx, gxy, gxz, gxw, gyx, gyy, gyz, gyw;
                gxx = p0.x + fmaf(2.f, p1.x, p.x);
                gxy = p0.y + fmaf(2.f, p1.y, p.y);
                gxz = p0.z + fmaf(2.f, p1.z, p.z);
                gxw = p0.w + fmaf(2.f, p1.w, p.w);
                gyx = q.x - q0.x;  gyy = q.y - q0.y;
                gyz = q.z - q0.z;  gyw = q.w - q0.w;
                acc[r].x += sqrt_approx(fmaf(gxx, gxx, fmaf(gyx, gyx, 1e-12f)));
                acc[r].y += sqrt_approx(fmaf(gxy, gxy, fmaf(gyy, gyy, 1e-12f)));
                acc[r].z += sqrt_approx(fmaf(gxz, gxz, fmaf(gyz, gyz, 1e-12f)));
                acc[r].w += sqrt_approx(fmaf(gxw, gxw, fmaf(gyw, gyw, 1e-12f)));
            }
            p0 = p1; p1 = p;
            q0 = q1; q1 = q;
        }
    }

    // Stage per-warp partials, then block-reduce across the 8 warps.
#pragma unroll
    for (int r = 0; r < RR; r++)
        *reinterpret_cast<float4*>(&s_acc[wid][r * TW + lane * 4]) = acc[r];
    __syncthreads();

    const float inv = 1.0f / (float)CC;
#pragma unroll
    for (int j = 0; j < (RR * TW) / 256; j++) {
        const int px = tid + 256 * j;          // 0..1023
        float s = 0.f;
#pragma unroll
        for (int w = 0; w < NWARPS; w++) s += s_acc[w][px];
        const int r   = px / TW;
        const int col = px % TW;
        out[((size_t)b * HH + (gh0 + r)) * WW + wq * TW + col] = s * inv;
    }
}

extern "C" void kernel_launch(void* const* d_in, const int* in_sizes, int n_in,
                              void* d_out, int out_size) {
    const float* x = (const float*)d_in[0];
    float* out = (float*)d_out;
    dim3 grid(WW / TW, HH / RR, BB);   // (2, 32, 16) = 1024 blocks
    sobel_mean_kernel<<<grid, 256>>>(x, out);
}

// round 2
// speedup vs baseline: 1.8369x; 1.8369x over previous
#include <cuda_runtime.h>

// Sobel edge magnitude + channel mean.
// x: [B=16, C=64, H=256, W=256] f32 -> out: [B,1,H,W] f32
//
// Separable: p_i = x[i][w+1]-x[i][w-1], q_i = x[i][w-1]+2x[i][w]+x[i][w+1]
//   gx(r) = p_r + 2 p_{r+1} + p_{r+2},   gy(r) = q_{r+2} - q_r
//
// R2 changes vs R1:
//  - No shuffles: column neighbors fetched with scalar LDGs that hit the same
//    128B lines as the vector loads (L1/L2 hits), issued in parallel.
//  - RR 8 -> 4 and smem 32KB -> 16KB to cut regs; __launch_bounds__(256,3)
//    targets 24 warps/SM instead of 16.

#define BB 16
#define CC 64
#define HH 256
#define WW 256
#define RR 4          // output rows per tile
#define NWARPS 8      // warps per block (channel stride)
#define TW 128        // columns per warp tile (32 lanes * 4)

__device__ __forceinline__ float sqrt_approx(float v) {
    float y;
    asm("sqrt.approx.f32 %0, %1;" : "=f"(y) : "f"(v));
    return y;
}

__global__ __launch_bounds__(256, 3)
void sobel_mean_kernel(const float* __restrict__ x, float* __restrict__ out) {
    const int wq   = blockIdx.x;   // column tile: 0..1
    const int hs   = blockIdx.y;   // row strip:   0..63
    const int b    = blockIdx.z;   // batch:       0..15
    const int tid  = threadIdx.x;
    const int wid  = tid >> 5;
    const int lane = tid & 31;

    const int gw4 = wq * TW + lane * 4;  // first of this lane's 4 columns
    const int gh0 = hs * RR;             // first output row of the strip

    __shared__ float s_acc[NWARPS][RR * TW];   // 16 KB

    float4 acc[RR];
#pragma unroll
    for (int r = 0; r < RR; r++) acc[r] = make_float4(0.f, 0.f, 0.f, 0.f);

    const bool has_left  = (gw4 != 0);
    const bool has_right = (gw4 + 4 != WW);

#pragma unroll 1
    for (int k = 0; k < CC / NWARPS; k++) {
        const int c = wid + NWARPS * k;
        const float* __restrict__ plane =
            x + ((size_t)(b * CC + c)) * (HH * WW);

        float4 p0, p1, q0, q1;   // rolling rows i-2, i-1
        p0 = p1 = q0 = q1 = make_float4(0.f, 0.f, 0.f, 0.f);

#pragma unroll
        for (int i = 0; i < RR + 2; i++) {
            const int gh = gh0 - 1 + i;
            const bool inb = (gh >= 0) && (gh < HH);
            const float* __restrict__ row = plane + gh * WW;

            float4 v = make_float4(0.f, 0.f, 0.f, 0.f);
            float lft = 0.f, rgt = 0.f;
            if (inb) {
                v = *reinterpret_cast<const float4*>(row + gw4);
                if (has_left)  lft = row[gw4 - 1];
                if (has_right) rgt = row[gw4 + 4];
            }

            float4 p, q;
            p.x = v.y - lft;  p.y = v.z - v.x;
            p.z = v.w - v.y;  p.w = rgt - v.z;
            q.x = fmaf(2.f, v.x, lft)  + v.y;
            q.y = fmaf(2.f, v.y, v.x)  + v.z;
            q.z = fmaf(2.f, v.z, v.y)  + v.w;
            q.w = fmaf(2.f, v.w, v.z)  + rgt;

            if (i >= 2) {
                const int r = i - 2;
                float gxx = p0.x + fmaf(2.f, p1.x, p.x);
                float gxy = p0.y + fmaf(2.f, p1.y, p.y);
                float gxz = p0.z + fmaf(2.f, p1.z, p.z);
                float gxw = p0.w + fmaf(2.f, p1.w, p.w);
                float gyx = q.x - q0.x;
                float gyy = q.y - q0.y;
                float gyz = q.z - q0.z;
                float gyw = q.w - q0.w;
                acc[r].x += sqrt_approx(fmaf(gxx, gxx, fmaf(gyx, gyx, 1e-12f)));
                acc[r].y += sqrt_approx(fmaf(gxy, gxy, fmaf(gyy, gyy, 1e-12f)));
                acc[r].z += sqrt_approx(fmaf(gxz, gxz, fmaf(gyz, gyz, 1e-12f)));
                acc[r].w += sqrt_approx(fmaf(gxw, gxw, fmaf(gyw, gyw, 1e-12f)));
            }
            p0 = p1; p1 = p;
            q0 = q1; q1 = q;
        }
    }

    // Stage per-warp partials, then block-reduce across the 8 warps.
#pragma unroll
    for (int r = 0; r < RR; r++)
        *reinterpret_cast<float4*>(&s_acc[wid][r * TW + lane * 4]) = acc[r];
    __syncthreads();

    const float inv = 1.0f / (float)CC;
#pragma unroll
    for (int j = 0; j < (RR * TW) / 256; j++) {
        const int px = tid + 256 * j;          // 0..511
        float s = 0.f;
#pragma unroll
        for (int w = 0; w < NWARPS; w++) s += s_acc[w][px];
        const int r   = px / TW;
        const int col = px % TW;
        out[((size_t)b * HH + (gh0 + r)) * WW + wq * TW + col] = s * inv;
    }
}

extern "C" void kernel_launch(void* const* d_in, const int* in_sizes, int n_in,
                              void* d_out, int out_size) {
    const float* x = (const float*)d_in[0];
    float* out = (float*)d_out;
    dim3 grid(WW / TW, HH / RR, BB);   // (2, 64, 16) = 2048 blocks
    sobel_mean_kernel<<<grid, 256>>>(x, out);
}

// round 3
// speedup vs baseline: 1.9290x; 1.0501x over previous
#include <cuda_runtime.h>

// Sobel edge magnitude + channel mean.
// x: [B=16, C=64, H=256, W=256] f32 -> out: [B,1,H,W] f32
//
// Separable: p_i = x[i][w+1]-x[i][w-1], q_i = x[i][w-1]+2x[i][w]+x[i][w+1]
//   gx(r) = p_r + 2 p_{r+1} + p_{r+2},   gy(r) = q_{r+2} - q_r
//
// R3 changes vs R2:
//  - __launch_bounds__(256, 4): force regs<=64 -> 32 warps/SM.
//  - EDGE template: interior strips (hs in [1,62]) run branch-free row loads;
//    only the 2 boundary strips pay the gh range checks. Two launches.

#define BB 16
#define CC 64
#define HH 256
#define WW 256
#define RR 4          // output rows per tile
#define NWARPS 8      // warps per block (channel stride)
#define TW 128        // columns per warp tile (32 lanes * 4)
#define HSTRIPS (HH / RR)

__device__ __forceinline__ float sqrt_approx(float v) {
    float y;
    asm("sqrt.approx.f32 %0, %1;" : "=f"(y) : "f"(v));
    return y;
}

template <bool EDGE>
__global__ __launch_bounds__(256, 4)
void sobel_mean_kernel(const float* __restrict__ x, float* __restrict__ out) {
    const int wq   = blockIdx.x;   // column tile: 0..1
    int hs;
    if (EDGE) hs = blockIdx.y ? (HSTRIPS - 1) : 0;   // boundary strips
    else      hs = blockIdx.y + 1;                    // interior: 1..62
    const int b    = blockIdx.z;
    const int tid  = threadIdx.x;
    const int wid  = tid >> 5;
    const int lane = tid & 31;

    const int gw4 = wq * TW + lane * 4;  // first of this lane's 4 columns
    const int gh0 = hs * RR;             // first output row of the strip

    __shared__ float s_acc[NWARPS][RR * TW];   // 16 KB

    float4 acc[RR];
#pragma unroll
    for (int r = 0; r < RR; r++) acc[r] = make_float4(0.f, 0.f, 0.f, 0.f);

    const bool has_left  = (gw4 != 0);
    const bool has_right = (gw4 + 4 != WW);

#pragma unroll 1
    for (int k = 0; k < CC / NWARPS; k++) {
        const int c = wid + NWARPS * k;
        const float* __restrict__ plane =
            x + ((size_t)(b * CC + c)) * (HH * WW);

        float4 p0, p1, q0, q1;   // rolling rows i-2, i-1
        p0 = p1 = q0 = q1 = make_float4(0.f, 0.f, 0.f, 0.f);

#pragma unroll
        for (int i = 0; i < RR + 2; i++) {
            const int gh = gh0 - 1 + i;
            const float* __restrict__ row = plane + gh * WW;

            float4 v;
            float lft, rgt;
            if (EDGE) {
                const bool inb = (gh >= 0) && (gh < HH);
                v = make_float4(0.f, 0.f, 0.f, 0.f);
                lft = 0.f; rgt = 0.f;
                if (inb) {
                    v = *reinterpret_cast<const float4*>(row + gw4);
                    if (has_left)  lft = row[gw4 - 1];
                    if (has_right) rgt = row[gw4 + 4];
                }
            } else {
                v = *reinterpret_cast<const float4*>(row + gw4);
                lft = has_left  ? row[gw4 - 1] : 0.f;
                rgt = has_right ? row[gw4 + 4] : 0.f;
            }

            float4 p, q;
            p.x = v.y - lft;  p.y = v.z - v.x;
            p.z = v.w - v.y;  p.w = rgt - v.z;
            q.x = fmaf(2.f, v.x, lft)  + v.y;
            q.y = fmaf(2.f, v.y, v.x)  + v.z;
            q.z = fmaf(2.f, v.z, v.y)  + v.w;
            q.w = fmaf(2.f, v.w, v.z)  + rgt;

            if (i >= 2) {
                const int r = i - 2;
                float gxx = p0.x + fmaf(2.f, p1.x, p.x);
                float gxy = p0.y + fmaf(2.f, p1.y, p.y);
                float gxz = p0.z + fmaf(2.f, p1.z, p.z);
                float gxw = p0.w + fmaf(2.f, p1.w, p.w);
                float gyx = q.x - q0.x;
                float gyy = q.y - q0.y;
                float gyz = q.z - q0.z;
                float gyw = q.w - q0.w;
                acc[r].x += sqrt_approx(fmaf(gxx, gxx, fmaf(gyx, gyx, 1e-12f)));
                acc[r].y += sqrt_approx(fmaf(gxy, gxy, fmaf(gyy, gyy, 1e-12f)));
                acc[r].z += sqrt_approx(fmaf(gxz, gxz, fmaf(gyz, gyz, 1e-12f)));
                acc[r].w += sqrt_approx(fmaf(gxw, gxw, fmaf(gyw, gyw, 1e-12f)));
            }
            p0 = p1; p1 = p;
            q0 = q1; q1 = q;
        }
    }

    // Stage per-warp partials, then block-reduce across the 8 warps.
#pragma unroll
    for (int r = 0; r < RR; r++)
        *reinterpret_cast<float4*>(&s_acc[wid][r * TW + lane * 4]) = acc[r];
    __syncthreads();

    const float inv = 1.0f / (float)CC;
#pragma unroll
    for (int j = 0; j < (RR * TW) / 256; j++) {
        const int px = tid + 256 * j;          // 0..511
        float s = 0.f;
#pragma unroll
        for (int w = 0; w < NWARPS; w++) s += s_acc[w][px];
        const int r   = px / TW;
        const int col = px % TW;
        out[((size_t)b * HH + (gh0 + r)) * WW + wq * TW + col] = s * inv;
    }
}

extern "C" void kernel_launch(void* const* d_in, const int* in_sizes, int n_in,
                              void* d_out, int out_size) {
    const float* x = (const float*)d_in[0];
    float* out = (float*)d_out;

    dim3 grid_int(WW / TW, HSTRIPS - 2, BB);   // (2, 62, 16) interior
    dim3 grid_edge(WW / TW, 2, BB);            // (2, 2, 16) top+bottom strips
    sobel_mean_kernel<false><<<grid_int, 256>>>(x, out);
    sobel_mean_kernel<true ><<<grid_edge, 256>>>(x, out);
}

// round 4
// speedup vs baseline: 2.2521x; 1.1675x over previous
#include <cuda_runtime.h>

// Sobel edge magnitude + channel mean.
// x: [B=16, C=64, H=256, W=256] f32 -> out: [B,1,H,W] f32
//
// Separable: p_i = x[i][w+1]-x[i][w-1], q_i = x[i][w-1]+2x[i][w]+x[i][w+1]
//   gx(r) = p_r + 2 p_{r+1} + p_{r+2},   gy(r) = q_{r+2} - q_r
//
// R4 changes vs R3:
//  - Single launch again (two-launch version serialized a ~20us edge tail).
//  - Row loop fully unrolled; only i==0 (hs==0) and i==RR+1 (hs==last) can be
//    out of bounds, guarded by block-uniform branches that vanish elsewhere.

#define BB 16
#define CC 64
#define HH 256
#define WW 256
#define RR 4          // output rows per tile
#define NWARPS 8      // warps per block (channel stride)
#define TW 128        // columns per warp tile (32 lanes * 4)
#define HSTRIPS (HH / RR)

__device__ __forceinline__ float sqrt_approx(float v) {
    float y;
    asm("sqrt.approx.f32 %0, %1;" : "=f"(y) : "f"(v));
    return y;
}

__global__ __launch_bounds__(256, 4)
void sobel_mean_kernel(const float* __restrict__ x, float* __restrict__ out) {
    const int wq   = blockIdx.x;   // column tile: 0..1
    const int hs   = blockIdx.y;   // row strip:   0..63
    const int b    = blockIdx.z;
    const int tid  = threadIdx.x;
    const int wid  = tid >> 5;
    const int lane = tid & 31;

    const int gw4 = wq * TW + lane * 4;  // first of this lane's 4 columns
    const int gh0 = hs * RR;             // first output row of the strip

    const bool top_oob = (hs == 0);
    const bool bot_oob = (hs == HSTRIPS - 1);

    __shared__ float s_acc[NWARPS][RR * TW];   // 16 KB

    float4 acc[RR];
#pragma unroll
    for (int r = 0; r < RR; r++) acc[r] = make_float4(0.f, 0.f, 0.f, 0.f);

    const bool has_left  = (gw4 != 0);
    const bool has_right = (gw4 + 4 != WW);

#pragma unroll 1
    for (int k = 0; k < CC / NWARPS; k++) {
        const int c = wid + NWARPS * k;
        const float* __restrict__ plane =
            x + ((size_t)(b * CC + c)) * (HH * WW);

        float4 p0, p1, q0, q1;   // rolling rows i-2, i-1
        p0 = p1 = q0 = q1 = make_float4(0.f, 0.f, 0.f, 0.f);

#pragma unroll
        for (int i = 0; i < RR + 2; i++) {
            const int gh = gh0 - 1 + i;
            const float* __restrict__ row = plane + gh * WW;

            // Only the first/last unrolled iterations can be OOB; the guard
            // is block-uniform and folds away for interior i.
            const bool oob = (i == 0 && top_oob) || (i == RR + 1 && bot_oob);

            float4 v;
            float lft, rgt;
            if (oob) {
                v = make_float4(0.f, 0.f, 0.f, 0.f);
                lft = 0.f; rgt = 0.f;
            } else {
                v = *reinterpret_cast<const float4*>(row + gw4);
                lft = has_left  ? row[gw4 - 1] : 0.f;
                rgt = has_right ? row[gw4 + 4] : 0.f;
            }

            float4 p, q;
            p.x = v.y - lft;  p.y = v.z - v.x;
            p.z = v.w - v.y;  p.w = rgt - v.z;
            q.x = fmaf(2.f, v.x, lft)  + v.y;
            q.y = fmaf(2.f, v.y, v.x)  + v.z;
            q.z = fmaf(2.f, v.z, v.y)  + v.w;
            q.w = fmaf(2.f, v.w, v.z)  + rgt;

            if (i >= 2) {
                const int r = i - 2;
                float gxx = p0.x + fmaf(2.f, p1.x, p.x);
                float gxy = p0.y + fmaf(2.f, p1.y, p.y);
                float gxz = p0.z + fmaf(2.f, p1.z, p.z);
                float gxw = p0.w + fmaf(2.f, p1.w, p.w);
                float gyx = q.x - q0.x;
                float gyy = q.y - q0.y;
                float gyz = q.z - q0.z;
                float gyw = q.w - q0.w;
                acc[r].x += sqrt_approx(fmaf(gxx, gxx, fmaf(gyx, gyx, 1e-12f)));
                acc[r].y += sqrt_approx(fmaf(gxy, gxy, fmaf(gyy, gyy, 1e-12f)));
                acc[r].z += sqrt_approx(fmaf(gxz, gxz, fmaf(gyz, gyz, 1e-12f)));
                acc[r].w += sqrt_approx(fmaf(gxw, gxw, fmaf(gyw, gyw, 1e-12f)));
            }
            p0 = p1; p1 = p;
            q0 = q1; q1 = q;
        }
    }

    // Stage per-warp partials, then block-reduce across the 8 warps.
#pragma unroll
    for (int r = 0; r < RR; r++)
        *reinterpret_cast<float4*>(&s_acc[wid][r * TW + lane * 4]) = acc[r];
    __syncthreads();

    const float inv = 1.0f / (float)CC;
#pragma unroll
    for (int j = 0; j < (RR * TW) / 256; j++) {
        const int px = tid + 256 * j;          // 0..511
        float s = 0.f;
#pragma unroll
        for (int w = 0; w < NWARPS; w++) s += s_acc[w][px];
        const int r   = px / TW;
        const int col = px % TW;
        out[((size_t)b * HH + (gh0 + r)) * WW + wq * TW + col] = s * inv;
    }
}

extern "C" void kernel_launch(void* const* d_in, const int* in_sizes, int n_in,
                              void* d_out, int out_size) {
    const float* x = (const float*)d_in[0];
    float* out = (float*)d_out;
    dim3 grid(WW / TW, HSTRIPS, BB);   // (2, 64, 16) = 2048 blocks
    sobel_mean_kernel<<<grid, 256>>>(x, out);
}

// round 5
// speedup vs baseline: 2.3268x; 1.0332x over previous
#include <cuda_runtime.h>

// Sobel edge magnitude + channel mean.
// x: [B=16, C=64, H=256, W=256] f32 -> out: [B,1,H,W] f32
//
// Separable: p_i = x[i][w+1]-x[i][w-1], q_i = x[i][w-1]+2x[i][w]+x[i][w+1]
//   gx(r) = p_r + 2 p_{r+1} + p_{r+2},   gy(r) = q_{r+2} - q_r
//
// R5 changes vs R4:
//  - All rolling math done in packed f32x2 (add.rn.f32x2 / fma.rn.f32x2),
//    2 lanes-values per instruction. Rolling p/q state stays packed, so only
//    l/c/r construction packs and only magnitudes unpack (for MUFU sqrt).
//  - Subtraction expressed as fma2(-1, a, b).

#define BB 16
#define CC 64
#define HH 256
#define WW 256
#define RR 4          // output rows per tile
#define NWARPS 8      // warps per block (channel stride)
#define TW 128        // columns per warp tile (32 lanes * 4)
#define HSTRIPS (HH / RR)

typedef unsigned long long u64;

__device__ __forceinline__ float sqrt_approx(float v) {
    float y;
    asm("sqrt.approx.f32 %0, %1;" : "=f"(y) : "f"(v));
    return y;
}
__device__ __forceinline__ u64 pk(float lo, float hi) {
    u64 r; asm("mov.b64 %0, {%1, %2};" : "=l"(r) : "f"(lo), "f"(hi)); return r;
}
__device__ __forceinline__ void upk(float& lo, float& hi, u64 v) {
    asm("mov.b64 {%0, %1}, %2;" : "=f"(lo), "=f"(hi) : "l"(v));
}
__device__ __forceinline__ u64 add2(u64 a, u64 b) {
    u64 r; asm("add.rn.f32x2 %0, %1, %2;" : "=l"(r) : "l"(a), "l"(b)); return r;
}
__device__ __forceinline__ u64 fma2(u64 a, u64 b, u64 c) {
    u64 r; asm("fma.rn.f32x2 %0, %1, %2, %3;" : "=l"(r) : "l"(a), "l"(b), "l"(c)); return r;
}

__global__ __launch_bounds__(256, 4)
void sobel_mean_kernel(const float* __restrict__ x, float* __restrict__ out) {
    const int wq   = blockIdx.x;   // column tile: 0..1
    const int hs   = blockIdx.y;   // row strip:   0..63
    const int b    = blockIdx.z;
    const int tid  = threadIdx.x;
    const int wid  = tid >> 5;
    const int lane = tid & 31;

    const int gw4 = wq * TW + lane * 4;  // first of this lane's 4 columns
    const int gh0 = hs * RR;             // first output row of the strip

    const bool top_oob = (hs == 0);
    const bool bot_oob = (hs == HSTRIPS - 1);

    __shared__ float s_acc[NWARPS][RR * TW];   // 16 KB

    const u64 TWO2 = pk(2.0f, 2.0f);
    const u64 NEG1 = pk(-1.0f, -1.0f);
    const u64 EPS2 = pk(1e-12f, 1e-12f);

    float4 acc[RR];
#pragma unroll
    for (int r = 0; r < RR; r++) acc[r] = make_float4(0.f, 0.f, 0.f, 0.f);

    const bool has_left  = (gw4 != 0);
    const bool has_right = (gw4 + 4 != WW);

#pragma unroll 1
    for (int k = 0; k < CC / NWARPS; k++) {
        const int c = wid + NWARPS * k;
        const float* __restrict__ plane =
            x + ((size_t)(b * CC + c)) * (HH * WW);

        // Rolling packed rows i-2, i-1 (lo = lanes {0,1}, hi = lanes {2,3})
        u64 p0l = 0, p0h = 0, p1l = 0, p1h = 0;
        u64 q0l = 0, q0h = 0, q1l = 0, q1h = 0;

#pragma unroll
        for (int i = 0; i < RR + 2; i++) {
            const int gh = gh0 - 1 + i;
            const float* __restrict__ row = plane + gh * WW;

            // Only first/last unrolled iterations can be OOB (block-uniform).
            const bool oob = (i == 0 && top_oob) || (i == RR + 1 && bot_oob);

            u64 pl, ph, ql, qh;
            if (oob) {
                pl = ph = ql = qh = 0;  // zero-padded row => p=q=0
            } else {
                const float4 v = *reinterpret_cast<const float4*>(row + gw4);
                const float lft = has_left  ? row[gw4 - 1] : 0.f;
                const float rgt = has_right ? row[gw4 + 4] : 0.f;

                // shifted vectors: l=(lft,v0,v1,v2) c=(v0..v3) r=(v1,v2,v3,rgt)
                const u64 ll = pk(lft, v.x);
                const u64 lh = pk(v.y, v.z);   // == r_lo
                const u64 cl = pk(v.x, v.y);
                const u64 ch = pk(v.z, v.w);
                const u64 rh = pk(v.w, rgt);

                pl = fma2(NEG1, ll, lh);               // r - l
                ph = fma2(NEG1, lh, rh);
                ql = add2(fma2(cl, TWO2, ll), lh);     // l + 2c + r
                qh = add2(fma2(ch, TWO2, lh), rh);
            }

            if (i >= 2) {
                const int r = i - 2;
                const u64 gxl = add2(fma2(p1l, TWO2, p0l), pl);
                const u64 gxh = add2(fma2(p1h, TWO2, p0h), ph);
                const u64 gyl = fma2(NEG1, q0l, ql);
                const u64 gyh = fma2(NEG1, q0h, qh);
                const u64 m_l = fma2(gxl, gxl, fma2(gyl, gyl, EPS2));
                const u64 m_h = fma2(gxh, gxh, fma2(gyh, gyh, EPS2));
                float m0, m1, m2, m3;
                upk(m0, m1, m_l);
                upk(m2, m3, m_h);
                acc[r].x += sqrt_approx(m0);
                acc[r].y += sqrt_approx(m1);
                acc[r].z += sqrt_approx(m2);
                acc[r].w += sqrt_approx(m3);
            }
            p0l = p1l; p0h = p1h; p1l = pl; p1h = ph;
            q0l = q1l; q0h = q1h; q1l = ql; q1h = qh;
        }
    }

    // Stage per-warp partials, then block-reduce across the 8 warps.
#pragma unroll
    for (int r = 0; r < RR; r++)
        *reinterpret_cast<float4*>(&s_acc[wid][r * TW + lane * 4]) = acc[r];
    __syncthreads();

    const float inv = 1.0f / (float)CC;
#pragma unroll
    for (int j = 0; j < (RR * TW) / 256; j++) {
        const int px = tid + 256 * j;          // 0..511
        float s = 0.f;
#pragma unroll
        for (int w = 0; w < NWARPS; w++) s += s_acc[w][px];
        const int r   = px / TW;
        const int col = px % TW;
        out[((size_t)b * HH + (gh0 + r)) * WW + wq * TW + col] = s * inv;
    }
}

extern "C" void kernel_launch(void* const* d_in, const int* in_sizes, int n_in,
                              void* d_out, int out_size) {
    const float* x = (const float*)d_in[0];
    float* out = (float*)d_out;
    dim3 grid(WW / TW, HSTRIPS, BB);   // (2, 64, 16) = 2048 blocks
    sobel_mean_kernel<<<grid, 256>>>(x, out);
}

// round 6
// speedup vs baseline: 2.8172x; 1.2108x over previous
#include <cuda_runtime.h>

// Sobel edge magnitude + channel mean.
// x: [B=16, C=64, H=256, W=256] f32 -> out: [B,1,H,W] f32
//
// Separable: p_i = x[i][w+1]-x[i][w-1], q_i = x[i][w-1]+2x[i][w]+x[i][w+1]
//   gx(r) = p_r + 2 p_{r+1} + p_{r+2},   gy(r) = q_{r+2} - q_r
//
// R6 changes vs R5:
//  - 2-channel interleave: each k-iteration processes channels c and c+8 in
//    the same unrolled row loop, so 6 independent LDGs issue per row step
//    (2x MLP per warp). __launch_bounds__(256,3) gives the regs room (<=84).

#define BB 16
#define CC 64
#define HH 256
#define WW 256
#define RR 4          // output rows per tile
#define NWARPS 8      // warps per block (channel stride)
#define TW 128        // columns per warp tile (32 lanes * 4)
#define HSTRIPS (HH / RR)

typedef unsigned long long u64;

__device__ __forceinline__ float sqrt_approx(float v) {
    float y;
    asm("sqrt.approx.f32 %0, %1;" : "=f"(y) : "f"(v));
    return y;
}
__device__ __forceinline__ u64 pk(float lo, float hi) {
    u64 r; asm("mov.b64 %0, {%1, %2};" : "=l"(r) : "f"(lo), "f"(hi)); return r;
}
__device__ __forceinline__ void upk(float& lo, float& hi, u64 v) {
    asm("mov.b64 {%0, %1}, %2;" : "=f"(lo), "=f"(hi) : "l"(v));
}
__device__ __forceinline__ u64 add2(u64 a, u64 b) {
    u64 r; asm("add.rn.f32x2 %0, %1, %2;" : "=l"(r) : "l"(a), "l"(b)); return r;
}
__device__ __forceinline__ u64 fma2(u64 a, u64 b, u64 c) {
    u64 r; asm("fma.rn.f32x2 %0, %1, %2, %3;" : "=l"(r) : "l"(a), "l"(b), "l"(c)); return r;
}

__global__ __launch_bounds__(256, 3)
void sobel_mean_kernel(const float* __restrict__ x, float* __restrict__ out) {
    const int wq   = blockIdx.x;   // column tile: 0..1
    const int hs   = blockIdx.y;   // row strip:   0..63
    const int b    = blockIdx.z;
    const int tid  = threadIdx.x;
    const int wid  = tid >> 5;
    const int lane = tid & 31;

    const int gw4 = wq * TW + lane * 4;  // first of this lane's 4 columns
    const int gh0 = hs * RR;             // first output row of the strip

    const bool top_oob = (hs == 0);
    const bool bot_oob = (hs == HSTRIPS - 1);

    __shared__ float s_acc[NWARPS][RR * TW];   // 16 KB

    const u64 TWO2 = pk(2.0f, 2.0f);
    const u64 NEG1 = pk(-1.0f, -1.0f);
    const u64 EPS2 = pk(1e-12f, 1e-12f);

    float4 acc[RR];
#pragma unroll
    for (int r = 0; r < RR; r++) acc[r] = make_float4(0.f, 0.f, 0.f, 0.f);

    const bool has_left  = (gw4 != 0);
    const bool has_right = (gw4 + 4 != WW);

#pragma unroll 1
    for (int k = 0; k < CC / NWARPS; k += 2) {
        // Two channels interleaved: c and c + NWARPS.
        const float* __restrict__ plane0 =
            x + ((size_t)(b * CC + wid + NWARPS * k)) * (HH * WW);
        const float* __restrict__ plane1 = plane0 + (size_t)NWARPS * (HH * WW);

        // Rolling packed rows i-2, i-1 for each channel
        u64 p0l[2] = {0, 0}, p0h[2] = {0, 0}, p1l[2] = {0, 0}, p1h[2] = {0, 0};
        u64 q0l[2] = {0, 0}, q0h[2] = {0, 0}, q1l[2] = {0, 0}, q1h[2] = {0, 0};

#pragma unroll
        for (int i = 0; i < RR + 2; i++) {
            const int gh = gh0 - 1 + i;
            const bool oob = (i == 0 && top_oob) || (i == RR + 1 && bot_oob);

            // ---- issue all 6 loads up front (2 planes) ----
            float4 v[2];
            float lft[2], rgt[2];
#pragma unroll
            for (int j = 0; j < 2; j++) {
                const float* __restrict__ row =
                    (j ? plane1 : plane0) + gh * WW;
                if (oob) {
                    v[j] = make_float4(0.f, 0.f, 0.f, 0.f);
                    lft[j] = 0.f; rgt[j] = 0.f;
                } else {
                    v[j]   = *reinterpret_cast<const float4*>(row + gw4);
                    lft[j] = has_left  ? row[gw4 - 1] : 0.f;
                    rgt[j] = has_right ? row[gw4 + 4] : 0.f;
                }
            }

            // ---- p/q for both channels ----
            u64 pl[2], ph[2], ql[2], qh[2];
#pragma unroll
            for (int j = 0; j < 2; j++) {
                const u64 ll = pk(lft[j], v[j].x);
                const u64 lh = pk(v[j].y, v[j].z);
                const u64 cl = pk(v[j].x, v[j].y);
                const u64 ch = pk(v[j].z, v[j].w);
                const u64 rh = pk(v[j].w, rgt[j]);
                pl[j] = fma2(NEG1, ll, lh);
                ph[j] = fma2(NEG1, lh, rh);
                ql[j] = add2(fma2(cl, TWO2, ll), lh);
                qh[j] = add2(fma2(ch, TWO2, lh), rh);
            }

            if (i >= 2) {
                const int r = i - 2;
                float s0 = 0.f, s1 = 0.f, s2 = 0.f, s3 = 0.f;
#pragma unroll
                for (int j = 0; j < 2; j++) {
                    const u64 gxl = add2(fma2(p1l[j], TWO2, p0l[j]), pl[j]);
                    const u64 gxh = add2(fma2(p1h[j], TWO2, p0h[j]), ph[j]);
                    const u64 gyl = fma2(NEG1, q0l[j], ql[j]);
                    const u64 gyh = fma2(NEG1, q0h[j], qh[j]);
                    const u64 m_l = fma2(gxl, gxl, fma2(gyl, gyl, EPS2));
                    const u64 m_h = fma2(gxh, gxh, fma2(gyh, gyh, EPS2));
                    float m0, m1, m2, m3;
                    upk(m0, m1, m_l);
                    upk(m2, m3, m_h);
                    s0 += sqrt_approx(m0);
                    s1 += sqrt_approx(m1);
                    s2 += sqrt_approx(m2);
                    s3 += sqrt_approx(m3);
                }
                acc[r].x += s0; acc[r].y += s1;
                acc[r].z += s2; acc[r].w += s3;
            }
#pragma unroll
            for (int j = 0; j < 2; j++) {
                p0l[j] = p1l[j]; p0h[j] = p1h[j]; p1l[j] = pl[j]; p1h[j] = ph[j];
                q0l[j] = q1l[j]; q0h[j] = q1h[j]; q1l[j] = ql[j]; q1h[j] = qh[j];
            }
        }
    }

    // Stage per-warp partials, then block-reduce across the 8 warps.
#pragma unroll
    for (int r = 0; r < RR; r++)
        *reinterpret_cast<float4*>(&s_acc[wid][r * TW + lane * 4]) = acc[r];
    __syncthreads();

    const float inv = 1.0f / (float)CC;
#pragma unroll
    for (int j = 0; j < (RR * TW) / 256; j++) {
        const int px = tid + 256 * j;          // 0..511
        float s = 0.f;
#pragma unroll
        for (int w = 0; w < NWARPS; w++) s += s_acc[w][px];
        const int r   = px / TW;
        const int col = px % TW;
        out[((size_t)b * HH + (gh0 + r)) * WW + wq * TW + col] = s * inv;
    }
}

extern "C" void kernel_launch(void* const* d_in, const int* in_sizes, int n_in,
                              void* d_out, int out_size) {
    const float* x = (const float*)d_in[0];
    float* out = (float*)d_out;
    dim3 grid(WW / TW, HSTRIPS, BB);   // (2, 64, 16) = 2048 blocks
    sobel_mean_kernel<<<grid, 256>>>(x, out);
}